// round 8
// baseline (speedup 1.0000x reference)
#include <cuda_runtime.h>
#include <cuda_fp16.h>
#include <cstdint>

#define MAXN 131072
// Packed tables: one uint4 (16B) per node per table.
// 12-bit unsigned q values (bias 2048) + fp16 row scale.
__device__ uint4 g_Y[MAXN];
__device__ uint4 g_Z[MAXN];

__device__ __forceinline__ uint32_t smem_u32(const void* p) {
    uint32_t a;
    asm("{ .reg .u64 t; cvta.to.shared.u64 t, %1; cvt.u32.u64 %0, t; }"
        : "=r"(a) : "l"(p));
    return a;
}

__device__ __forceinline__ void mbar_init(uint32_t mbar, uint32_t cnt) {
    asm volatile("mbarrier.init.shared.b64 [%0], %1;" :: "r"(mbar), "r"(cnt) : "memory");
}

__device__ __forceinline__ void mbar_expect_tx(uint32_t mbar, uint32_t bytes) {
    asm volatile("mbarrier.arrive.expect_tx.shared.b64 _, [%0], %1;"
                 :: "r"(mbar), "r"(bytes) : "memory");
}

__device__ __forceinline__ void mbar_wait_parity(uint32_t mbar, uint32_t parity) {
    asm volatile(
        "{\n\t"
        ".reg .pred P1;\n\t"
        "WAIT_LOOP_%=:\n\t"
        "mbarrier.try_wait.parity.acquire.cta.shared::cta.b64 P1, [%0], %1, 0x989680;\n\t"
        "@P1 bra.uni WAIT_DONE_%=;\n\t"
        "bra.uni WAIT_LOOP_%=;\n\t"
        "WAIT_DONE_%=:\n\t"
        "}"
        :: "r"(mbar), "r"(parity) : "memory");
}

// 16-byte async bulk copy global->shared, counted on mbar via complete_tx
__device__ __forceinline__ void bulk16(uint32_t dst, const void* src, uint32_t mbar) {
    asm volatile(
        "cp.async.bulk.shared::cluster.global.mbarrier::complete_tx::bytes [%0], [%1], %2, [%3];"
        :: "r"(dst), "l"(src), "r"(16u), "r"(mbar) : "memory");
}

__device__ __forceinline__ uint4 pack_row(const float* v) {
    float mx = fabsf(v[0]);
#pragma unroll
    for (int o = 1; o < 9; o++) mx = fmaxf(mx, fabsf(v[o]));
    // quantize against the STORED (fp16-rounded) scale: no systematic scale error
    __half hs = __float2half_rn(fmaxf(mx, 1e-20f) * (1.0f / 2047.0f));
    float inv = 1.0f / __half2float(hs);

    unsigned int q[9];
#pragma unroll
    for (int o = 0; o < 9; o++) {
        int qi = __float2int_rn(v[o] * inv);
        qi = max(-2047, min(2047, qi));
        q[o] = (unsigned int)(qi + 2048);
    }
    uint4 w;
    w.x = q[0] | (q[1] << 12) | (q[2] << 24);
    w.y = (q[2] >> 8) | (q[3] << 4) | (q[4] << 16) | (q[5] << 28);
    w.z = (q[5] >> 4) | (q[6] << 8) | (q[7] << 20);
    w.w = q[8] | ((unsigned int)__half_as_ushort(hs) << 16);
    return w;
}

// ---------------------------------------------------------------------------
// Kernel 1: per-node precompute + 12-bit quantization (unchanged from R7).
// ---------------------------------------------------------------------------
__global__ void __launch_bounds__(256)
node_precompute(const float* __restrict__ x,
                const int* __restrict__ node_types,
                const float* __restrict__ W,
                int N) {
    __shared__ __align__(16) float sW[9 * 72];
    __shared__ __align__(16) float xs[256 * 36];

    for (int i = threadIdx.x; i < 9 * 72; i += blockDim.x) sW[i] = W[i];

    int base = blockIdx.x * 256;
    const float4* xp = reinterpret_cast<const float4*>(x);
#pragma unroll
    for (int i = 0; i < 8; i++) {
        int lin = i * 256 + threadIdx.x;
        int nl  = lin >> 3;
        int cp  = lin & 7;
        if (base + nl < N) {
            float4 v = xp[(size_t)(base + nl) * 8 + cp];
            *reinterpret_cast<float4*>(xs + nl * 36 + cp * 4) = v;
        }
    }
    __syncthreads();

    int n = base + threadIdx.x;
    if (n >= N) return;

    float4 xr[8];
    const float4* myrow = reinterpret_cast<const float4*>(xs + threadIdx.x * 36);
#pragma unroll
    for (int i = 0; i < 8; i++) xr[i] = myrow[i];

    int t = node_types[n];

    float yv[9], zv[9];
#pragma unroll
    for (int o = 0; o < 9; o++) {
        const float4* w4 = reinterpret_cast<const float4*>(sW + o * 72);
        float accY = sW[o * 72 + 64 + t];
        float accZ = sW[o * 72 + 68 + t];
#pragma unroll
        for (int i = 0; i < 8; i++) {
            float4 wa = w4[i];
            float4 wb = w4[8 + i];
            accY = fmaf(xr[i].x, wa.x, accY);
            accY = fmaf(xr[i].y, wa.y, accY);
            accY = fmaf(xr[i].z, wa.z, accY);
            accY = fmaf(xr[i].w, wa.w, accY);
            accZ = fmaf(xr[i].x, wb.x, accZ);
            accZ = fmaf(xr[i].y, wb.y, accZ);
            accZ = fmaf(xr[i].z, wb.z, accZ);
            accZ = fmaf(xr[i].w, wb.w, accZ);
        }
        yv[o] = accY;
        zv[o] = accZ;
    }

    g_Y[n] = pack_row(yv);
    g_Z[n] = pack_row(zv);
}

__device__ __forceinline__ void unpack_row(uint4 w, float q[9], float& s) {
    q[0] = (float)( w.x        & 0xFFFu);
    q[1] = (float)((w.x >> 12) & 0xFFFu);
    q[2] = (float)(((w.x >> 24) | (w.y << 8)) & 0xFFFu);
    q[3] = (float)((w.y >> 4)  & 0xFFFu);
    q[4] = (float)((w.y >> 16) & 0xFFFu);
    q[5] = (float)(((w.y >> 28) | (w.z << 4)) & 0xFFFu);
    q[6] = (float)((w.z >> 8)  & 0xFFFu);
    q[7] = (float)( w.z >> 20);
    q[8] = (float)( w.w        & 0xFFFu);
    s = __half2float(__ushort_as_half((unsigned short)(w.w >> 16)));
}

__device__ __forceinline__ void decode_edge_sum(uint4 yw, uint4 zw, float* a) {
    float qy[9], qz[9], sy, sz;
    unpack_row(yw, qy, sy);
    unpack_row(zw, qz, sz);
    float c = -2048.0f * (sy + sz);
#pragma unroll
    for (int o = 0; o < 9; o++)
        a[o] = fmaf(sy, qy[o], fmaf(sz, qz[o], c));
}

__device__ __forceinline__ unsigned int tanh_h2(float lo, float hi) {
    __half2 h = __floats2half2_rn(lo, hi);
    unsigned int u;
    { union { __half2 h; unsigned int u; } cvt; cvt.h = h; u = cvt.u; }
    asm("tanh.approx.f16x2 %0, %0;" : "+r"(u));
    return u;
}

// ---------------------------------------------------------------------------
// Kernel 2: gathers via 16B cp.async.bulk (UBLKCP) into smem — bypasses the
// LSU address-divergence replay floor. Decode from smem, SIMD tanh, smem
// buffer reused for half2 output staging, coalesced float2 stores.
// ---------------------------------------------------------------------------
#define EPB 512   // edges per block (256 threads x 2)

__global__ void __launch_bounds__(256)
edge_kernel(const int* __restrict__ ei,
            float* __restrict__ out,
            int E) {
    // 16KB: Y rows [0..511], Z rows [512..1023]; reused for output staging
    __shared__ __align__(16) unsigned char smem_raw[EPB * 2 * 16];
    __shared__ __align__(8) unsigned long long mbar_storage;

    uint4* rows = reinterpret_cast<uint4*>(smem_raw);
    uint32_t mbar  = smem_u32(&mbar_storage);
    uint32_t rbase = smem_u32(smem_raw);

    if (threadIdx.x == 0) mbar_init(mbar, 1);
    __syncthreads();

    int t  = blockIdx.x * 256 + threadIdx.x;   // pair index
    int e0 = 2 * t;
    int blockBase = blockIdx.x * EPB;
    int eCnt = min(EPB, E - blockBase);        // edges in this block (>0)

    bool v0 = (e0 < E), v1 = (e0 + 1 < E);
    int le = 2 * threadIdx.x;

    if (v1) {
        int2 sp, dp;
        if ((E & 1) == 0) {
            sp = reinterpret_cast<const int2*>(ei)[t];
            dp = reinterpret_cast<const int2*>(ei + E)[t];
        } else {
            sp = make_int2(ei[e0], ei[e0 + 1]);
            dp = make_int2(ei[E + e0], ei[E + e0 + 1]);
        }
        bulk16(rbase + (uint32_t)le * 16u,            &g_Y[sp.x], mbar);
        bulk16(rbase + (uint32_t)(le + 1) * 16u,      &g_Y[sp.y], mbar);
        bulk16(rbase + (uint32_t)(EPB + le) * 16u,    &g_Z[dp.x], mbar);
        bulk16(rbase + (uint32_t)(EPB + le + 1) * 16u,&g_Z[dp.y], mbar);
    } else if (v0) {
        int s0 = ei[e0], d0 = ei[E + e0];
        bulk16(rbase + (uint32_t)le * 16u,         &g_Y[s0], mbar);
        bulk16(rbase + (uint32_t)(EPB + le) * 16u, &g_Z[d0], mbar);
    }

    if (threadIdx.x == 0) mbar_expect_tx(mbar, (uint32_t)eCnt * 32u);
    mbar_wait_parity(mbar, 0);

    // decode from smem (in-bounds smem reads even for invalid edges; results
    // for invalid edges are never stored to gmem)
    uint4 y0 = rows[le];
    uint4 y1 = rows[le + 1];
    uint4 z0 = rows[EPB + le];
    uint4 z1 = rows[EPB + le + 1];

    float a[18];
    decode_edge_sum(y0, z0, a);
    decode_edge_sum(y1, z1, a + 9);

    unsigned int rh[9];
#pragma unroll
    for (int k = 0; k < 9; k++) rh[k] = tanh_h2(a[2 * k], a[2 * k + 1]);

    __syncthreads();   // all threads done reading rows; safe to reuse buffer

    unsigned int* ob = reinterpret_cast<unsigned int*>(smem_raw);
#pragma unroll
    for (int k = 0; k < 9; k++) ob[threadIdx.x * 9 + k] = rh[k];
    __syncthreads();

    // coalesced output: 2304 half2 per block -> float2 stores
    long long lim    = (long long)E * 9;               // total floats
    long long g2base = (long long)blockIdx.x * 2304;   // half2 index base
#pragma unroll
    for (int it = 0; it < 9; it++) {
        int i = it * 256 + threadIdx.x;                // 0..2303
        long long g2 = g2base + i;
        long long f0 = 2 * g2;
        if (f0 + 1 < lim) {
            union { unsigned int u; __half2 h; } cvt; cvt.u = ob[i];
            reinterpret_cast<float2*>(out)[g2] = __half22float2(cvt.h);
        } else if (f0 < lim) {
            union { unsigned int u; __half2 h; } cvt; cvt.u = ob[i];
            out[f0] = __low2float(cvt.h);
        }
    }
}

extern "C" void kernel_launch(void* const* d_in, const int* in_sizes, int n_in,
                              void* d_out, int out_size) {
    // metadata order: x [N,32] f32, edge_index [2,E] i32, node_types [N] i32, W [9,72] f32
    const float* x  = (const float*)d_in[0];
    const int*   ei = (const int*)d_in[1];
    const int*   nt = (const int*)d_in[2];
    const float* W  = (const float*)d_in[3];
    float* out = (float*)d_out;

    int N = in_sizes[2];
    int E = in_sizes[1] / 2;

    node_precompute<<<(N + 255) / 256, 256>>>(x, nt, W, N);
    edge_kernel<<<(E + EPB - 1) / EPB, 256>>>(ei, out, E);
}

// round 9
// speedup vs baseline: 1.4159x; 1.4159x over previous
#include <cuda_runtime.h>
#include <cuda_fp16.h>
#include <cstdint>

#define MAXN 131072
#define EPB 512   // edges per block (256 threads x 2)

// Packed tables: one uint4 (16B) per node per table.
// 12-bit unsigned q values (bias 2048) + fp16 row scale.
__device__ uint4 g_Y[MAXN];
__device__ uint4 g_Z[MAXN];

// fused-kernel barrier state (reset to 0 by the last block every launch)
__device__ int g_start_cnt = 0;
__device__ int g_done_cnt  = 0;

// ---------------- helpers ----------------
__device__ __forceinline__ unsigned long long packf2(float lo, float hi) {
    unsigned long long r;
    asm("mov.b64 %0, {%1, %2};" : "=l"(r) : "f"(lo), "f"(hi));
    return r;
}
__device__ __forceinline__ void unpackf2(unsigned long long v, float& lo, float& hi) {
    asm("mov.b64 {%0, %1}, %2;" : "=f"(lo), "=f"(hi) : "l"(v));
}
__device__ __forceinline__ void fma2(unsigned long long& acc,
                                     unsigned long long a, unsigned long long b) {
    asm("fma.rn.f32x2 %0, %1, %2, %0;" : "+l"(acc) : "l"(a), "l"(b));
}

__device__ __forceinline__ unsigned int tanh_h2(float lo, float hi) {
    __half2 h = __floats2half2_rn(lo, hi);
    unsigned int u;
    { union { __half2 h; unsigned int u; } cvt; cvt.h = h; u = cvt.u; }
    asm("tanh.approx.f16x2 %0, %0;" : "+r"(u));
    return u;
}

__device__ __forceinline__ uint4 pack_row(const float* v) {
    float mx = fabsf(v[0]);
#pragma unroll
    for (int o = 1; o < 9; o++) mx = fmaxf(mx, fabsf(v[o]));
    // quantize against the STORED (fp16-rounded) scale: no systematic scale error
    __half hs = __float2half_rn(fmaxf(mx, 1e-20f) * (1.0f / 2047.0f));
    float inv = __fdividef(1.0f, __half2float(hs));

    unsigned int q[9];
#pragma unroll
    for (int o = 0; o < 9; o++) {
        int qi = __float2int_rn(v[o] * inv);
        qi = max(-2047, min(2047, qi));
        q[o] = (unsigned int)(qi + 2048);
    }
    uint4 w;
    w.x = q[0] | (q[1] << 12) | (q[2] << 24);
    w.y = (q[2] >> 8) | (q[3] << 4) | (q[4] << 16) | (q[5] << 28);
    w.z = (q[5] >> 4) | (q[6] << 8) | (q[7] << 20);
    w.w = q[8] | ((unsigned int)__half_as_ushort(hs) << 16);
    return w;
}

__device__ __forceinline__ void unpack_row(uint4 w, float q[9], float& s) {
    q[0] = (float)( w.x        & 0xFFFu);
    q[1] = (float)((w.x >> 12) & 0xFFFu);
    q[2] = (float)(((w.x >> 24) | (w.y << 8)) & 0xFFFu);
    q[3] = (float)((w.y >> 4)  & 0xFFFu);
    q[4] = (float)((w.y >> 16) & 0xFFFu);
    q[5] = (float)(((w.y >> 28) | (w.z << 4)) & 0xFFFu);
    q[6] = (float)((w.z >> 8)  & 0xFFFu);
    q[7] = (float)( w.z >> 20);
    q[8] = (float)( w.w        & 0xFFFu);
    s = __half2float(__ushort_as_half((unsigned short)(w.w >> 16)));
}

__device__ __forceinline__ void decode_edge_sum(uint4 yw, uint4 zw, float* a) {
    float qy[9], qz[9], sy, sz;
    unpack_row(yw, qy, sy);
    unpack_row(zw, qz, sz);
    float c = -2048.0f * (sy + sz);
#pragma unroll
    for (int o = 0; o < 9; o++)
        a[o] = fmaf(sy, qy[o], fmaf(sz, qz[o], c));
}

// ---------------------------------------------------------------------------
// Fused kernel:
//  phase 1 (blocks < preBlocks): per-node Y/Z precompute (f32x2 FMAs) + 12-bit pack
//  device-wide flag barrier (release: threadfence+atomicAdd; acquire: poll+fence)
//  phase 2 (all blocks): R7 edge gather/decode/tanh/store
// __launch_bounds__(256,3) guarantees >=3 resident blocks/SM (444 >= preBlocks=391),
// so every precompute block is in wave 1 -> no deadlock.
// ---------------------------------------------------------------------------
__global__ void __launch_bounds__(256, 3)
fused_kernel(const float* __restrict__ x,
             const int* __restrict__ ei,
             const int* __restrict__ nt,
             const float* __restrict__ W,
             float* __restrict__ out,
             int N, int E, int preBlocks, int edgeBlocks) {
    // interleaved weight pairs: sWp[o*36+d] = (W[o][d], W[o][32+d]) for d<32,
    //                           sWp[o*36+32+t] = (W[o][64+t], W[o][68+t])
    __shared__ __align__(16) float2 sWp[9 * 36];
    __shared__ __align__(16) char sraw[256 * 36 * 4];   // xs staging / output staging
    float* xs = reinterpret_cast<float*>(sraw);
    unsigned int* ob = reinterpret_cast<unsigned int*>(sraw);

    const int bid = blockIdx.x;
    const int tid = threadIdx.x;

    // ---------------- phase 1: precompute ----------------
    if (bid < preBlocks) {
        for (int i = tid; i < 9 * 36; i += 256) {
            int o = i / 36, d = i % 36;
            float a, b;
            if (d < 32) { a = W[o * 72 + d];        b = W[o * 72 + 32 + d]; }
            else        { a = W[o * 72 + 64 + (d - 32)]; b = W[o * 72 + 68 + (d - 32)]; }
            sWp[i] = make_float2(a, b);
        }
        int base = bid * 256;
        const float4* xp = reinterpret_cast<const float4*>(x);
#pragma unroll
        for (int i = 0; i < 8; i++) {
            int lin = i * 256 + tid;
            int nl  = lin >> 3;
            int cp  = lin & 7;
            if (base + nl < N)
                *reinterpret_cast<float4*>(xs + nl * 36 + cp * 4) =
                    xp[(size_t)(base + nl) * 8 + cp];
        }
        __syncthreads();

        int n = base + tid;
        if (n < N) {
            int t = nt[n];
            unsigned long long acc[9];
#pragma unroll
            for (int o = 0; o < 9; o++)
                acc[o] = *reinterpret_cast<const unsigned long long*>(&sWp[o * 36 + 32 + t]);

            const float2* xrow = reinterpret_cast<const float2*>(xs + tid * 36);
#pragma unroll
            for (int d2 = 0; d2 < 16; d2++) {
                float2 xv = xrow[d2];
                unsigned long long x0 = packf2(xv.x, xv.x);
                unsigned long long x1 = packf2(xv.y, xv.y);
#pragma unroll
                for (int o = 0; o < 9; o++) {
                    ulonglong2 w2 = *reinterpret_cast<const ulonglong2*>(&sWp[o * 36 + 2 * d2]);
                    fma2(acc[o], x0, w2.x);
                    fma2(acc[o], x1, w2.y);
                }
            }
            float yv[9], zv[9];
#pragma unroll
            for (int o = 0; o < 9; o++) unpackf2(acc[o], yv[o], zv[o]);
            g_Y[n] = pack_row(yv);
            g_Z[n] = pack_row(zv);
        }
        __threadfence();       // release our table rows
        __syncthreads();
        if (tid == 0) atomicAdd(&g_start_cnt, 1);
    }

    // ---------------- device-wide barrier ----------------
    if (tid == 0) {
        while (*(volatile int*)&g_start_cnt < preBlocks) __nanosleep(64);
        __threadfence();       // acquire
    }
    __syncthreads();

    // ---------------- phase 2: edges (R7 body) ----------------
    if (bid < edgeBlocks) {
        int pt = bid * 256 + tid;   // pair index
        int e0 = 2 * pt;

        uint4 y0, y1, z0, z1;
        bool v0 = (e0 < E), v1 = (e0 + 1 < E);

        if (v1) {
            int2 sp, dp;
            if ((E & 1) == 0) {
                sp = reinterpret_cast<const int2*>(ei)[pt];
                dp = reinterpret_cast<const int2*>(ei + E)[pt];
            } else {
                sp = make_int2(ei[e0], ei[e0 + 1]);
                dp = make_int2(ei[E + e0], ei[E + e0 + 1]);
            }
            y0 = __ldg(&g_Y[sp.x]);
            z0 = __ldg(&g_Z[dp.x]);
            y1 = __ldg(&g_Y[sp.y]);
            z1 = __ldg(&g_Z[dp.y]);
        } else if (v0) {
            int s0 = ei[e0], d0 = ei[E + e0];
            y0 = __ldg(&g_Y[s0]);
            z0 = __ldg(&g_Z[d0]);
            y1 = make_uint4(0, 0, 0, 0);
            z1 = make_uint4(0, 0, 0, 0);
        } else {
            y0 = y1 = z0 = z1 = make_uint4(0, 0, 0, 0);
        }

        float a[18];
        decode_edge_sum(y0, z0, a);
        decode_edge_sum(y1, z1, a + 9);

        unsigned int rh[9];
#pragma unroll
        for (int k = 0; k < 9; k++) rh[k] = tanh_h2(a[2 * k], a[2 * k + 1]);

        __syncthreads();   // smem reuse (xs -> ob) for precompute blocks
#pragma unroll
        for (int k = 0; k < 9; k++) ob[tid * 9 + k] = rh[k];
        __syncthreads();

        // coalesced output: 2304 half2 per block -> float2 stores
        long long lim    = (long long)E * 9;              // total floats
        long long g2base = (long long)bid * 2304;         // half2 index base
#pragma unroll
        for (int it = 0; it < 9; it++) {
            int i = it * 256 + tid;                       // 0..2303
            long long g2 = g2base + i;
            long long f0 = 2 * g2;
            if (f0 + 1 < lim) {
                union { unsigned int u; __half2 h; } cvt; cvt.u = ob[i];
                reinterpret_cast<float2*>(out)[g2] = __half22float2(cvt.h);
            } else if (f0 < lim) {
                union { unsigned int u; __half2 h; } cvt; cvt.u = ob[i];
                out[f0] = __low2float(cvt.h);
            }
        }
    }

    // ---------------- epilogue: reset barrier counters for next replay ----------
    __syncthreads();
    if (tid == 0) {
        int dcount = atomicAdd(&g_done_cnt, 1) + 1;
        if (dcount == (int)gridDim.x) {
            g_done_cnt  = 0;
            g_start_cnt = 0;
        }
    }
}

extern "C" void kernel_launch(void* const* d_in, const int* in_sizes, int n_in,
                              void* d_out, int out_size) {
    // metadata order: x [N,32] f32, edge_index [2,E] i32, node_types [N] i32, W [9,72] f32
    const float* x  = (const float*)d_in[0];
    const int*   ei = (const int*)d_in[1];
    const int*   nt = (const int*)d_in[2];
    const float* W  = (const float*)d_in[3];
    float* out = (float*)d_out;

    int N = in_sizes[2];
    int E = in_sizes[1] / 2;

    int preBlocks  = (N + 255) / 256;          // 391
    int edgeBlocks = (E + EPB - 1) / EPB;      // 3125
    int grid = max(preBlocks, edgeBlocks);

    fused_kernel<<<grid, 256>>>(x, ei, nt, W, out, N, E, preBlocks, edgeBlocks);
}